// round 16
// baseline (speedup 1.0000x reference)
#include <cuda_runtime.h>
#include <cuda_bf16.h>
#include <math.h>
#include <stdint.h>

// Problem constants
#define T_DIM   36
#define NPOLES  40
#define KDIM    160
#define PDIM    4096
#define PCOLS   64           // p columns per CTA
#define NCTA    128
#define NTHREADS 512         // 16 warps, 4/SMSP (forces <=128 regs)
#define MAXIT   100
#define LAM_C   0.1f
#define TOL_C   1e-4f

// LDS.64 pairbank = (S/2 mod 16)*g + i4 = 4g + i4 -> exactly 2 lanes/bank (optimal)
#define YSTR    168          // y fp32 column stride (words)
#define ZSTR    72           // z fp32 column stride (words)

// ---- dynamic smem layout (bytes) ----
#define RED_OFF   0          // 16 floats
#define STOP_OFF  64
#define TTS_OFF   128        // 100 floats
#define A1H_OFF   1024                  // D48 frags: 30*512 = 15360
#define A1L_OFF   (A1H_OFF + 15360)
#define A2H_OFF   (A1L_OFF + 15360)     // -linv*D^T frags, M padded to 192: 36*512 = 18432
#define A2L_OFF   (A2H_OFF + 18432)
#define DTY_OFF   (A2L_OFF + 18432)     // 80 real c-frags * 512 = 40960
#define Y_OFF     (DTY_OFF + 40960)     // 64 * 168 * 4 = 43008
#define ZA_OFF    (Y_OFF + 43008)       // 64 * 72 * 4 = 18432
#define ZB_OFF    (ZA_OFF + 18432)
#define SMEM_TOTAL (ZB_OFF + 18432)     // 189440
// startup staging (inside Y region, consumed before y zeroing):
#define DICT_STAGE Y_OFF                // dict [36][160] fp32 = 23040
#define X_STAGE   (Y_OFF + 23040)       // x tile [36][64] fp32 = 9216

// ---------------- device globals ----------------
__device__ float    g_Dmat[T_DIM * KDIM];
__device__ float    g_lambd;
__device__ float    g_linv;
__device__ float    g_tts[MAXIT];
__device__ float    g_part[NCTA];
__device__ unsigned g_count;
__device__ unsigned g_gen;

// ---------------- helpers ----------------
__device__ __forceinline__ void mma_bf16(float* c, const uint32_t* a, const uint32_t* b) {
    asm volatile(
        "mma.sync.aligned.m16n8k16.row.col.f32.bf16.bf16.f32 "
        "{%0,%1,%2,%3}, {%4,%5,%6,%7}, {%8,%9}, {%0,%1,%2,%3};"
        : "+f"(c[0]), "+f"(c[1]), "+f"(c[2]), "+f"(c[3])
        : "r"(a[0]), "r"(a[1]), "r"(a[2]), "r"(a[3]), "r"(b[0]), "r"(b[1]));
}
__device__ __forceinline__ void split_pack(float v0, float v1, uint32_t& hi, uint32_t& lo) {
    asm("cvt.rn.bf16x2.f32 %0, %1, %2;" : "=r"(hi) : "f"(v1), "f"(v0));
    float h0 = __uint_as_float(hi << 16);
    float h1 = __uint_as_float(hi & 0xffff0000u);
    asm("cvt.rn.bf16x2.f32 %0, %1, %2;" : "=r"(lo) : "f"(v1 - h1), "f"(v0 - h0));
}
__device__ __forceinline__ float warp_sum(float v) {
    v += __shfl_xor_sync(0xFFFFFFFFu, v, 16);
    v += __shfl_xor_sync(0xFFFFFFFFu, v, 8);
    v += __shfl_xor_sync(0xFFFFFFFFu, v, 4);
    v += __shfl_xor_sync(0xFFFFFFFFu, v, 2);
    v += __shfl_xor_sync(0xFFFFFFFFu, v, 1);
    return v;
}

// ---------------- setup ----------------
__global__ void setup_kernel(const float* __restrict__ Drr,
                             const float* __restrict__ Dtheta) {
    __shared__ float rbuf[32];
    const int tid = threadIdx.x;

    if (tid < KDIM) {
        const int j = tid;
        const int g = j / NPOLES;
        const int n = j % NPOLES;
        const float rr = Drr[n];
        const float th = Dtheta[n];
        float vals[T_DIM];
        float pr = 1.0f, n2 = 0.0f;
        for (int i = 0; i < T_DIM; ++i) {
            float ang  = (float)i * th;
            float base = (g < 2) ? cosf(ang) : sinf(ang);
            float v = pr * base;
            if ((g & 1) && (i & 1)) v = -v;
            vals[i] = v; n2 += v * v; pr *= rr;
        }
        float G  = (n2 == 0.0f) ? 6.0f : sqrtf(n2);
        float gi = 1.0f / G;
        for (int i = 0; i < T_DIM; ++i) g_Dmat[i * KDIM + j] = vals[i] * gi;
    }
    __syncthreads();

    float sq = 0.0f;
    for (int e = tid; e < KDIM * KDIM; e += 1024) {
        int i = e / KDIM, jj = e % KDIM;
        float s = 0.0f;
        for (int t = 0; t < T_DIM; ++t)
            s += g_Dmat[t * KDIM + i] * g_Dmat[t * KDIM + jj];
        sq += s * s;
    }
    float ws = warp_sum(sq);
    if ((tid & 31) == 0) rbuf[tid >> 5] = ws;
    __syncthreads();
    if (tid == 0) {
        float tot = 0.0f;
        for (int i = 0; i < 32; ++i) tot += rbuf[i];
        float L = sqrtf(tot);
        float linv = 1.0f / L;
        g_linv  = linv;
        g_lambd = LAM_C * linv;
        double t = 1.0;
        for (int k = 0; k < MAXIT; ++k) {
            double tn = (1.0 + sqrt(1.0 + 4.0 * t * t)) * 0.5;
            g_tts[k] = (float)((t - 1.0) / tn);
            t = tn;
        }
        g_count = 0;
        g_gen   = 0;
    }
    if (tid < NCTA) g_part[tid] = 0.0f;
}

// ---------------- persistent FISTA kernel (16 warps, M padded to 192) ------
// stage1: warp (s1h=w>>3 ks-half, s1s=w&7 8-col stripe): z partial -> Za/Zb.
// stage2: warp (wm=w>>2 in 0..3: 3 m-frags, wn=w&3: 16-col stripe, nt=2):
//         acc = DtY - linv*D^T @ (za+zb).  Frags fr=wm*3+j; fr>=10 are zero pad.
__global__ void __launch_bounds__(NTHREADS, 1)
fista_kernel(const float* __restrict__ x_in, float* __restrict__ out) {
    extern __shared__ __align__(16) char smem[];
    float* red    = (float*)(smem + RED_OFF);
    int*   s_stop = (int*)(smem + STOP_OFF);
    float* tts_s  = (float*)(smem + TTS_OFF);

    const int tid = threadIdx.x;
    const int wid = tid >> 5;
    const int l   = tid & 31;
    const int wm  = wid >> 2;          // stage2: 0..3 (48-row band, 3 frags)
    const int wn  = wid & 3;           // stage2: 0..3 (16-col stripe)
    const int s1h = wid >> 3;          // stage1: ks half
    const int s1s = wid & 7;           // stage1: 8-col stripe
    const int g   = l >> 2;
    const int i4  = l & 3;
    const int cta = blockIdx.x;
    const int b   = cta >> 6;
    const int p0  = (cta & 63) * PCOLS;

    const float linv  = g_linv;
    const float lambd = g_lambd;

    // ---- stage dict and x tile fp32; copy tts ----
    for (int e = tid; e < T_DIM * KDIM; e += NTHREADS)
        *(float*)(smem + DICT_STAGE + e * 4) = g_Dmat[e];
    for (int e = tid; e < T_DIM * PCOLS; e += NTHREADS) {
        int t = e >> 6, pp = e & 63;
        *(float*)(smem + X_STAGE + e * 4) = x_in[(b * T_DIM + t) * PDIM + p0 + pp];
    }
    if (tid < MAXIT) tts_s[tid] = g_tts[tid];
    __syncthreads();

    // ---- DtY = linv * D^T x -> DTY smem (real frags only) ----
    {
        float dty[24];
        #pragma unroll
        for (int v = 0; v < 24; ++v) dty[v] = 0.0f;
        const float* Ds = (const float*)(smem + DICT_STAGE);
        const float* Xs = (const float*)(smem + X_STAGE);
        for (int t = 0; t < T_DIM; ++t) {
            float dr[6], xc[4];
            #pragma unroll
            for (int j = 0; j < 3; ++j) {
                int fr = wm * 3 + j;
                dr[j * 2]     = (fr < 10) ? Ds[t * KDIM + fr * 16 + g] : 0.0f;
                dr[j * 2 + 1] = (fr < 10) ? Ds[t * KDIM + fr * 16 + g + 8] : 0.0f;
            }
            #pragma unroll
            for (int nt = 0; nt < 2; ++nt) {
                xc[nt * 2]     = Xs[t * PCOLS + wn * 16 + nt * 8 + i4 * 2];
                xc[nt * 2 + 1] = Xs[t * PCOLS + wn * 16 + nt * 8 + i4 * 2 + 1];
            }
            #pragma unroll
            for (int j = 0; j < 3; ++j)
                #pragma unroll
                for (int nt = 0; nt < 2; ++nt)
                    #pragma unroll
                    for (int q = 0; q < 4; ++q)
                        dty[(j * 2 + nt) * 4 + q] =
                            fmaf(dr[j * 2 + (q >> 1)], xc[nt * 2 + (q & 1)],
                                 dty[(j * 2 + nt) * 4 + q]);
        }
        __syncthreads();   // staging consumed (Y region reused below)
        #pragma unroll
        for (int j = 0; j < 3; ++j) {
            int fr = wm * 3 + j;
            if (fr < 10) {
                #pragma unroll
                for (int nt = 0; nt < 2; ++nt) {
                    int f = fr * 8 + wn * 2 + nt;
                    *(float4*)(smem + DTY_OFF + (f * 32 + l) * 16) =
                        make_float4(dty[(j * 2 + nt) * 4 + 0] * linv,
                                    dty[(j * 2 + nt) * 4 + 1] * linv,
                                    dty[(j * 2 + nt) * 4 + 2] * linv,
                                    dty[(j * 2 + nt) * 4 + 3] * linv);
                }
            }
        }
    }

    // ---- pack stage-1 operand: D48[48,160] (rows>=36 zero), f1 = mt*10+ks ----
    for (int e = tid; e < 30 * 32 * 4; e += NTHREADS) {
        int frag = e >> 7;
        int lane = (e >> 2) & 31;
        int reg  = e & 3;
        int mt   = frag / 10, ks = frag % 10;
        int r = mt * 16 + (lane >> 2) + ((reg & 1) ? 8 : 0);
        int k = ks * 16 + (lane & 3) * 2 + ((reg & 2) ? 8 : 0);
        float v0 = (r < T_DIM) ? g_Dmat[r * KDIM + k] : 0.0f;
        float v1 = (r < T_DIM) ? g_Dmat[r * KDIM + k + 1] : 0.0f;
        uint32_t hi, lo;
        split_pack(v0, v1, hi, lo);
        *(uint32_t*)(smem + A1H_OFF + e * 4) = hi;
        *(uint32_t*)(smem + A1L_OFF + e * 4) = lo;
    }
    // ---- pack stage-2 operand: (-linv)*D^T [192 rows padded, 48], f2 = fr*3+ks
    for (int e = tid; e < 36 * 32 * 4; e += NTHREADS) {
        int frag = e >> 7;
        int lane = (e >> 2) & 31;
        int reg  = e & 3;
        int fr   = frag / 3, ks = frag % 3;
        int r = fr * 16 + (lane >> 2) + ((reg & 1) ? 8 : 0);
        int k = ks * 16 + (lane & 3) * 2 + ((reg & 2) ? 8 : 0);
        float v0 = (k < T_DIM && r < KDIM) ? -linv * g_Dmat[k * KDIM + r] : 0.0f;
        float v1 = (k + 1 < T_DIM && r < KDIM) ? -linv * g_Dmat[(k + 1) * KDIM + r] : 0.0f;
        uint32_t hi, lo;
        split_pack(v0, v1, hi, lo);
        *(uint32_t*)(smem + A2H_OFF + e * 4) = hi;
        *(uint32_t*)(smem + A2L_OFF + e * 4) = lo;
    }
    // ---- zero y (fp32) ----
    for (int e = tid; e < PCOLS * YSTR; e += NTHREADS)
        *(float*)(smem + Y_OFF + e * 4) = 0.0f;

    float xold[24], yreg[24];
    #pragma unroll
    for (int v = 0; v < 24; ++v) { xold[v] = 0.0f; yreg[v] = 0.0f; }
    __syncthreads();

    const float* Yp = (const float*)(smem + Y_OFF);
    const float* Za = (const float*)(smem + ZA_OFF);
    const float* Zb = (const float*)(smem + ZB_OFF);

    // ---- main FISTA loop ----
    for (int it = 0; it < MAXIT; ++it) {
        // ===== stage 1: z partial (ks in [5*s1h,5*s1h+5)), 8-col stripe =====
        float z1[3][4];
        #pragma unroll
        for (int mt = 0; mt < 3; ++mt)
            #pragma unroll
            for (int q = 0; q < 4; ++q) z1[mt][q] = 0.0f;

        #pragma unroll
        for (int kk = 0; kk < 5; ++kk) {
            const int ks = s1h * 5 + kk;
            const float* yrow = Yp + (s1s * 8 + g) * YSTR + ks * 16 + i4 * 2;
            float2 v0 = *(const float2*)(yrow);
            float2 v1 = *(const float2*)(yrow + 8);
            uint32_t bh[2], bl[2];
            split_pack(v0.x, v0.y, bh[0], bl[0]);
            split_pack(v1.x, v1.y, bh[1], bl[1]);
            uint32_t a1h[3][4], a1l[3][4];
            #pragma unroll
            for (int mt = 0; mt < 3; ++mt) {
                int fi = (mt * 10 + ks) * 32 + l;
                uint4 Ah = *(const uint4*)(smem + A1H_OFF + fi * 16);
                uint4 Al = *(const uint4*)(smem + A1L_OFF + fi * 16);
                a1h[mt][0] = Ah.x; a1h[mt][1] = Ah.y; a1h[mt][2] = Ah.z; a1h[mt][3] = Ah.w;
                a1l[mt][0] = Al.x; a1l[mt][1] = Al.y; a1l[mt][2] = Al.z; a1l[mt][3] = Al.w;
            }
            #pragma unroll
            for (int mt = 0; mt < 3; ++mt) mma_bf16(z1[mt], a1h[mt], bh);
            #pragma unroll
            for (int mt = 0; mt < 3; ++mt) mma_bf16(z1[mt], a1h[mt], bl);
            #pragma unroll
            for (int mt = 0; mt < 3; ++mt) mma_bf16(z1[mt], a1l[mt], bh);
        }
        // write partial z (buffer by ks-half)
        {
            float* zdst = (float*)(smem + (s1h ? ZB_OFF : ZA_OFF));
            #pragma unroll
            for (int mt = 0; mt < 3; ++mt)
                #pragma unroll
                for (int q = 0; q < 4; ++q) {
                    int row = mt * 16 + g + ((q >> 1) << 3);
                    int col = s1s * 8 + i4 * 2 + (q & 1);
                    zdst[col * ZSTR + row] = z1[mt][q];
                }
        }

        // join the gen-poll
        if (it > 0 && tid == 0) {
            while (*((volatile unsigned*)&g_gen) < (unsigned)it) { __nanosleep(32); }
        }
        __syncthreads();   // sync_Z

        // stop decision for it-1, overlapped with stage 2 (w0 only)
        if (it > 0 && wid == 0) {
            float s = *((volatile float*)(g_part + l));
            s += *((volatile float*)(g_part + l + 32));
            s += *((volatile float*)(g_part + l + 64));
            s += *((volatile float*)(g_part + l + 96));
            float tot = warp_sum(s);
            if (l == 0) {
                float denom = (it == 1) ? (float)PDIM : (float)KDIM;
                *s_stop = (sqrtf(tot) < TOL_C * denom) ? 1 : 0;
            }
        }

        // ===== stage 2: acc = DtY + (-linv*D^T) @ (za+zb) =====
        float acc[6][4];
        #pragma unroll
        for (int j = 0; j < 3; ++j) {
            int fr = wm * 3 + j;
            #pragma unroll
            for (int nt = 0; nt < 2; ++nt) {
                if (fr < 10) {
                    int f = fr * 8 + wn * 2 + nt;
                    float4 c = *(const float4*)(smem + DTY_OFF + (f * 32 + l) * 16);
                    acc[j * 2 + nt][0] = c.x; acc[j * 2 + nt][1] = c.y;
                    acc[j * 2 + nt][2] = c.z; acc[j * 2 + nt][3] = c.w;
                } else {
                    acc[j * 2 + nt][0] = 0.0f; acc[j * 2 + nt][1] = 0.0f;
                    acc[j * 2 + nt][2] = 0.0f; acc[j * 2 + nt][3] = 0.0f;
                }
            }
        }

        #pragma unroll
        for (int ks = 0; ks < 3; ++ks) {
            uint32_t bh[2][2], bl[2][2];
            #pragma unroll
            for (int nt = 0; nt < 2; ++nt) {
                const int zoff = (wn * 16 + nt * 8 + g) * ZSTR + ks * 16 + i4 * 2;
                float2 a0 = *(const float2*)(Za + zoff);
                float2 a1 = *(const float2*)(Za + zoff + 8);
                float2 b0 = *(const float2*)(Zb + zoff);
                float2 b1 = *(const float2*)(Zb + zoff + 8);
                split_pack(a0.x + b0.x, a0.y + b0.y, bh[nt][0], bl[nt][0]);
                split_pack(a1.x + b1.x, a1.y + b1.y, bh[nt][1], bl[nt][1]);
            }
            uint32_t ah[3][4], al[3][4];
            #pragma unroll
            for (int j = 0; j < 3; ++j) {
                int fi = ((wm * 3 + j) * 3 + ks) * 32 + l;
                uint4 Ah = *(const uint4*)(smem + A2H_OFF + fi * 16);
                uint4 Al = *(const uint4*)(smem + A2L_OFF + fi * 16);
                ah[j][0] = Ah.x; ah[j][1] = Ah.y; ah[j][2] = Ah.z; ah[j][3] = Ah.w;
                al[j][0] = Al.x; al[j][1] = Al.y; al[j][2] = Al.z; al[j][3] = Al.w;
            }
            #pragma unroll
            for (int j = 0; j < 3; ++j)
                #pragma unroll
                for (int nt = 0; nt < 2; ++nt)
                    mma_bf16(acc[j * 2 + nt], ah[j], bh[nt]);
            #pragma unroll
            for (int j = 0; j < 3; ++j)
                #pragma unroll
                for (int nt = 0; nt < 2; ++nt)
                    mma_bf16(acc[j * 2 + nt], ah[j], bl[nt]);
            #pragma unroll
            for (int j = 0; j < 3; ++j)
                #pragma unroll
                for (int nt = 0; nt < 2; ++nt)
                    mma_bf16(acc[j * 2 + nt], al[j], bh[nt]);
        }

        const float tt = tts_s[it];
        float dsum = 0.0f;

        // epilogue (speculative): v = acc + y_reg ; shrink ; momentum
        #pragma unroll
        for (int j = 0; j < 3; ++j) {
            int fr = wm * 3 + j;
            #pragma unroll
            for (int nt = 0; nt < 2; ++nt)
                #pragma unroll
                for (int q = 0; q < 4; ++q) {
                    int ix  = (j * 2 + nt) * 4 + q;
                    float v  = acc[j * 2 + nt][q] + yreg[ix];
                    float a  = fabsf(v) - lambd;
                    float xn = (a > 0.0f) ? copysignf(a, v) : 0.0f;
                    float xo = xold[ix];
                    float d  = xn - xo;
                    dsum = fmaf(d, d, dsum);
                    float yn = fmaf(tt, d, xn);
                    xold[ix] = xn;
                    yreg[ix] = yn;
                    if (fr < 10) {
                        int row = fr * 16 + g + ((q >> 1) << 3);
                        int col = wn * 16 + nt * 8 + i4 * 2 + (q & 1);
                        *(float*)(smem + Y_OFF + (col * YSTR + row) * 4) = yn;
                    }
                }
        }

        float ws = warp_sum(dsum);
        if (l == 0) red[wid] = ws;
        __syncthreads();   // sync_B

        if (it > 0 && *s_stop) {
            float inv_tt = 1.0f / tt;
            #pragma unroll
            for (int v = 0; v < 24; ++v)
                xold[v] = xold[v] - (yreg[v] - xold[v]) * inv_tt;
            break;
        }

        // publish partial + arrive (no wait; decision deferred)
        if (tid == 0) {
            float s = red[0];
            #pragma unroll
            for (int i = 1; i < 16; ++i) s += red[i];
            g_part[cta] = s;
            __threadfence();
            unsigned tk = atomicAdd(&g_count, 1);
            if (tk == (unsigned)(NCTA - 1)) {
                g_count = 0;
                __threadfence();
                atomicAdd(&g_gen, 1);
            }
        }
    }

    // ---- output ----
    #pragma unroll
    for (int j = 0; j < 3; ++j) {
        int fr = wm * 3 + j;
        if (fr < 10) {
            #pragma unroll
            for (int nt = 0; nt < 2; ++nt)
                #pragma unroll
                for (int q = 0; q < 4; ++q) {
                    int row = fr * 16 + g + ((q >> 1) << 3);
                    int col = wn * 16 + nt * 8 + i4 * 2 + (q & 1);
                    out[((size_t)b * KDIM + row) * PDIM + p0 + col] =
                        xold[(j * 2 + nt) * 4 + q];
                }
        }
    }
}

// ---------------- launch ----------------
extern "C" void kernel_launch(void* const* d_in, const int* in_sizes, int n_in,
                              void* d_out, int out_size) {
    const float* Drr    = (const float*)d_in[0];
    const float* Dtheta = (const float*)d_in[1];
    const float* x      = (const float*)d_in[2];
    float* out = (float*)d_out;

    cudaFuncSetAttribute(fista_kernel, cudaFuncAttributeMaxDynamicSharedMemorySize, SMEM_TOTAL);
    setup_kernel<<<1, 1024>>>(Drr, Dtheta);
    fista_kernel<<<NCTA, NTHREADS, SMEM_TOTAL>>>(x, out);
}

// round 17
// speedup vs baseline: 1.2406x; 1.2406x over previous
#include <cuda_runtime.h>
#include <cuda_bf16.h>
#include <math.h>
#include <stdint.h>

// Problem constants
#define T_DIM   36
#define NPOLES  40
#define KDIM    160
#define PDIM    4096
#define PCOLS   64           // p columns per CTA
#define NCTA    128
#define NTHREADS 256         // 8 warps
#define MAXIT   100
#define LAM_C   0.1f
#define TOL_C   1e-4f

// LDS.64 pairbank = (S/2 mod 16)*g + i4 = 4g + i4 -> exactly 2 lanes/bank (optimal)
#define YSTR    168          // y fp32 column stride (words)
#define ZSTR    72           // z fp32 column stride (words)

// ---- dynamic smem layout (bytes) ----
#define RED_OFF   0          // 8 floats (per-warp partials)
#define STOP_OFF  64
#define TTS_OFF   128        // 100 floats
#define A1H_OFF   1024                  // D48 frags: 30*512 = 15360
#define A1L_OFF   (A1H_OFF + 15360)
#define A2H_OFF   (A1L_OFF + 15360)     // -linv*D^T frags
#define A2L_OFF   (A2H_OFF + 15360)
#define DTY_OFF   (A2L_OFF + 15360)     // 80 c-frags * 512 = 40960
#define Y_OFF     (DTY_OFF + 40960)     // 64 * 168 * 4 = 43008
#define Z_OFF     (Y_OFF + 43008)       // 64 * 72 * 4 = 18432
#define SMEM_TOTAL (Z_OFF + 18432)      // 164864
// startup staging (inside Y region, consumed before y zeroing):
#define DICT_STAGE Y_OFF                // dict [36][160] fp32 = 23040
#define X_STAGE   (Y_OFF + 23040)       // x tile [36][64] fp32 = 9216

// ---------------- device globals ----------------
__device__ float    g_Dmat[T_DIM * KDIM];   // [t][k] normalized dictionary
__device__ float    g_lambd;
__device__ float    g_linv;
__device__ float    g_tts[MAXIT];
// 4-deep ring of tagged partials: word = ((it+1) << 32) | float_bits(partial)
__device__ unsigned long long g_sync[4 * NCTA];

// ---------------- helpers ----------------
__device__ __forceinline__ void mma_bf16(float* c, const uint32_t* a, const uint32_t* b) {
    asm volatile(
        "mma.sync.aligned.m16n8k16.row.col.f32.bf16.bf16.f32 "
        "{%0,%1,%2,%3}, {%4,%5,%6,%7}, {%8,%9}, {%0,%1,%2,%3};"
        : "+f"(c[0]), "+f"(c[1]), "+f"(c[2]), "+f"(c[3])
        : "r"(a[0]), "r"(a[1]), "r"(a[2]), "r"(a[3]), "r"(b[0]), "r"(b[1]));
}
__device__ __forceinline__ void split_pack(float v0, float v1, uint32_t& hi, uint32_t& lo) {
    asm("cvt.rn.bf16x2.f32 %0, %1, %2;" : "=r"(hi) : "f"(v1), "f"(v0));
    float h0 = __uint_as_float(hi << 16);
    float h1 = __uint_as_float(hi & 0xffff0000u);
    asm("cvt.rn.bf16x2.f32 %0, %1, %2;" : "=r"(lo) : "f"(v1 - h1), "f"(v0 - h0));
}
__device__ __forceinline__ float warp_sum(float v) {
    v += __shfl_xor_sync(0xFFFFFFFFu, v, 16);
    v += __shfl_xor_sync(0xFFFFFFFFu, v, 8);
    v += __shfl_xor_sync(0xFFFFFFFFu, v, 4);
    v += __shfl_xor_sync(0xFFFFFFFFu, v, 2);
    v += __shfl_xor_sync(0xFFFFFFFFu, v, 1);
    return v;
}

// ---------------- setup (1024 threads) ----------------
__global__ void setup_kernel(const float* __restrict__ Drr,
                             const float* __restrict__ Dtheta) {
    __shared__ float rbuf[32];
    const int tid = threadIdx.x;

    if (tid < KDIM) {
        const int j = tid;
        const int g = j / NPOLES;
        const int n = j % NPOLES;
        const float rr = Drr[n];
        const float th = Dtheta[n];
        float vals[T_DIM];
        float pr = 1.0f, n2 = 0.0f;
        for (int i = 0; i < T_DIM; ++i) {
            float ang  = (float)i * th;
            float base = (g < 2) ? cosf(ang) : sinf(ang);
            float v = pr * base;
            if ((g & 1) && (i & 1)) v = -v;
            vals[i] = v; n2 += v * v; pr *= rr;
        }
        float G  = (n2 == 0.0f) ? 6.0f : sqrtf(n2);
        float gi = 1.0f / G;
        for (int i = 0; i < T_DIM; ++i) g_Dmat[i * KDIM + j] = vals[i] * gi;
    }
    __syncthreads();

    float sq = 0.0f;
    for (int e = tid; e < KDIM * KDIM; e += 1024) {
        int i = e / KDIM, jj = e % KDIM;
        float s = 0.0f;
        for (int t = 0; t < T_DIM; ++t)
            s += g_Dmat[t * KDIM + i] * g_Dmat[t * KDIM + jj];
        sq += s * s;
    }
    float ws = warp_sum(sq);
    if ((tid & 31) == 0) rbuf[tid >> 5] = ws;
    __syncthreads();
    if (tid == 0) {
        float tot = 0.0f;
        for (int i = 0; i < 32; ++i) tot += rbuf[i];
        float L = sqrtf(tot);
        float linv = 1.0f / L;
        g_linv  = linv;
        g_lambd = LAM_C * linv;
        double t = 1.0;
        for (int k = 0; k < MAXIT; ++k) {
            double tn = (1.0 + sqrt(1.0 + 4.0 * t * t)) * 0.5;
            g_tts[k] = (float)((t - 1.0) / tn);
            t = tn;
        }
    }
    if (tid < 4 * NCTA) g_sync[tid] = 0ULL;
}

// ---------------- persistent FISTA kernel (factorized, 8 warps) ------------
__global__ void __launch_bounds__(NTHREADS, 1)
fista_kernel(const float* __restrict__ x_in, float* __restrict__ out) {
    extern __shared__ __align__(16) char smem[];
    float* red    = (float*)(smem + RED_OFF);
    int*   s_stop = (int*)(smem + STOP_OFF);
    float* tts_s  = (float*)(smem + TTS_OFF);

    const int tid = threadIdx.x;
    const int wid = tid >> 5;
    const int l   = tid & 31;
    const int wm  = wid >> 2;          // stage2: 0..1 (80-row half)
    const int wn  = wid & 3;           // stage2: 0..3 (16-col stripe)
    const int g   = l >> 2;
    const int i4  = l & 3;
    const int cta = blockIdx.x;
    const int b   = cta >> 6;
    const int p0  = (cta & 63) * PCOLS;

    const float linv  = g_linv;
    const float lambd = g_lambd;

    // ---- stage dict and x tile fp32; copy tts ----
    for (int e = tid; e < T_DIM * KDIM; e += NTHREADS)
        *(float*)(smem + DICT_STAGE + e * 4) = g_Dmat[e];
    for (int e = tid; e < T_DIM * PCOLS; e += NTHREADS) {
        int t = e >> 6, pp = e & 63;
        *(float*)(smem + X_STAGE + e * 4) = x_in[(b * T_DIM + t) * PDIM + p0 + pp];
    }
    if (tid < MAXIT) tts_s[tid] = g_tts[tid];
    __syncthreads();

    // ---- DtY = linv * D^T x -> DTY smem (c-frag layout) ----
    {
        float dty[40];
        #pragma unroll
        for (int v = 0; v < 40; ++v) dty[v] = 0.0f;
        const float* Ds = (const float*)(smem + DICT_STAGE);
        const float* Xs = (const float*)(smem + X_STAGE);
        for (int t = 0; t < T_DIM; ++t) {
            float dr[10], xc[4];
            #pragma unroll
            for (int mt = 0; mt < 5; ++mt) {
                dr[mt * 2]     = Ds[t * KDIM + wm * 80 + mt * 16 + g];
                dr[mt * 2 + 1] = Ds[t * KDIM + wm * 80 + mt * 16 + g + 8];
            }
            #pragma unroll
            for (int nt = 0; nt < 2; ++nt) {
                xc[nt * 2]     = Xs[t * PCOLS + wn * 16 + nt * 8 + i4 * 2];
                xc[nt * 2 + 1] = Xs[t * PCOLS + wn * 16 + nt * 8 + i4 * 2 + 1];
            }
            #pragma unroll
            for (int mt = 0; mt < 5; ++mt)
                #pragma unroll
                for (int nt = 0; nt < 2; ++nt)
                    #pragma unroll
                    for (int q = 0; q < 4; ++q)
                        dty[(mt * 2 + nt) * 4 + q] =
                            fmaf(dr[mt * 2 + (q >> 1)], xc[nt * 2 + (q & 1)],
                                 dty[(mt * 2 + nt) * 4 + q]);
        }
        __syncthreads();   // staging consumed (Y region reused below)

        #pragma unroll
        for (int mt = 0; mt < 5; ++mt)
            #pragma unroll
            for (int nt = 0; nt < 2; ++nt) {
                int f = (wm * 5 + mt) * 8 + wn * 2 + nt;
                *(float4*)(smem + DTY_OFF + (f * 32 + l) * 16) =
                    make_float4(dty[(mt * 2 + nt) * 4 + 0] * linv,
                                dty[(mt * 2 + nt) * 4 + 1] * linv,
                                dty[(mt * 2 + nt) * 4 + 2] * linv,
                                dty[(mt * 2 + nt) * 4 + 3] * linv);
            }
    }

    // ---- pack stage-1 operand: D48[48,160] (rows>=36 zero), f1 = mt*10+ks ----
    for (int e = tid; e < 30 * 32 * 4; e += NTHREADS) {
        int frag = e >> 7;
        int lane = (e >> 2) & 31;
        int reg  = e & 3;
        int mt   = frag / 10, ks = frag % 10;
        int r = mt * 16 + (lane >> 2) + ((reg & 1) ? 8 : 0);
        int k = ks * 16 + (lane & 3) * 2 + ((reg & 2) ? 8 : 0);
        float v0 = (r < T_DIM) ? g_Dmat[r * KDIM + k] : 0.0f;
        float v1 = (r < T_DIM) ? g_Dmat[r * KDIM + k + 1] : 0.0f;
        uint32_t hi, lo;
        split_pack(v0, v1, hi, lo);
        *(uint32_t*)(smem + A1H_OFF + e * 4) = hi;
        *(uint32_t*)(smem + A1L_OFF + e * 4) = lo;
    }
    // ---- pack stage-2 operand: (-linv)*D^T [160,48] (cols>=36 zero), f2 = mt*3+ks
    for (int e = tid; e < 30 * 32 * 4; e += NTHREADS) {
        int frag = e >> 7;
        int lane = (e >> 2) & 31;
        int reg  = e & 3;
        int mt   = frag / 3, ks = frag % 3;
        int r = mt * 16 + (lane >> 2) + ((reg & 1) ? 8 : 0);
        int k = ks * 16 + (lane & 3) * 2 + ((reg & 2) ? 8 : 0);
        float v0 = (k < T_DIM) ? -linv * g_Dmat[k * KDIM + r] : 0.0f;
        float v1 = (k + 1 < T_DIM) ? -linv * g_Dmat[(k + 1) * KDIM + r] : 0.0f;
        uint32_t hi, lo;
        split_pack(v0, v1, hi, lo);
        *(uint32_t*)(smem + A2H_OFF + e * 4) = hi;
        *(uint32_t*)(smem + A2L_OFF + e * 4) = lo;
    }
    // ---- zero y (fp32) ----
    for (int e = tid; e < PCOLS * YSTR; e += NTHREADS)
        *(float*)(smem + Y_OFF + e * 4) = 0.0f;

    float xold[40], yreg[40];
    #pragma unroll
    for (int v = 0; v < 40; ++v) { xold[v] = 0.0f; yreg[v] = 0.0f; }
    __syncthreads();

    const float* Yp = (const float*)(smem + Y_OFF);
    const float* Zp = (const float*)(smem + Z_OFF);
    float*       Zw = (float*)(smem + Z_OFF);

    // ---- main FISTA loop ----
    for (int it = 0; it < MAXIT; ++it) {
        // ===== stage 1: z[48, 8 cols of warp] = D48 @ y, full ks =====
        float z1[3][4];
        #pragma unroll
        for (int mt = 0; mt < 3; ++mt)
            #pragma unroll
            for (int q = 0; q < 4; ++q) z1[mt][q] = 0.0f;

        #pragma unroll 2
        for (int ks = 0; ks < 10; ++ks) {
            const float* yrow = Yp + (wid * 8 + g) * YSTR + ks * 16 + i4 * 2;
            float2 v0 = *(const float2*)(yrow);
            float2 v1 = *(const float2*)(yrow + 8);
            uint32_t bh[2], bl[2];
            split_pack(v0.x, v0.y, bh[0], bl[0]);
            split_pack(v1.x, v1.y, bh[1], bl[1]);
            uint32_t a1h[3][4], a1l[3][4];
            #pragma unroll
            for (int mt = 0; mt < 3; ++mt) {
                int fi = (mt * 10 + ks) * 32 + l;
                uint4 Ah = *(const uint4*)(smem + A1H_OFF + fi * 16);
                uint4 Al = *(const uint4*)(smem + A1L_OFF + fi * 16);
                a1h[mt][0] = Ah.x; a1h[mt][1] = Ah.y; a1h[mt][2] = Ah.z; a1h[mt][3] = Ah.w;
                a1l[mt][0] = Al.x; a1l[mt][1] = Al.y; a1l[mt][2] = Al.z; a1l[mt][3] = Al.w;
            }
            #pragma unroll
            for (int mt = 0; mt < 3; ++mt) mma_bf16(z1[mt], a1h[mt], bh);
            #pragma unroll
            for (int mt = 0; mt < 3; ++mt) mma_bf16(z1[mt], a1h[mt], bl);
            #pragma unroll
            for (int mt = 0; mt < 3; ++mt) mma_bf16(z1[mt], a1l[mt], bh);
        }
        #pragma unroll
        for (int mt = 0; mt < 3; ++mt)
            #pragma unroll
            for (int q = 0; q < 4; ++q) {
                int row = mt * 16 + g + ((q >> 1) << 3);
                int col = wid * 8 + i4 * 2 + (q & 1);
                Zw[col * ZSTR + row] = z1[mt][q];
            }

        // hoisted (hazard-free) loads: acc init + stage2 ks=0 A-frags
        float acc[10][4];
        #pragma unroll
        for (int mt = 0; mt < 5; ++mt)
            #pragma unroll
            for (int nt = 0; nt < 2; ++nt) {
                int f = (wm * 5 + mt) * 8 + wn * 2 + nt;
                float4 c = *(const float4*)(smem + DTY_OFF + (f * 32 + l) * 16);
                acc[mt * 2 + nt][0] = c.x; acc[mt * 2 + nt][1] = c.y;
                acc[mt * 2 + nt][2] = c.z; acc[mt * 2 + nt][3] = c.w;
            }
        uint32_t ah0[5][4], al0[5][4];
        #pragma unroll
        for (int mt = 0; mt < 5; ++mt) {
            int fi = ((wm * 5 + mt) * 3 + 0) * 32 + l;
            uint4 Ah = *(const uint4*)(smem + A2H_OFF + fi * 16);
            uint4 Al = *(const uint4*)(smem + A2L_OFF + fi * 16);
            ah0[mt][0] = Ah.x; ah0[mt][1] = Ah.y; ah0[mt][2] = Ah.z; ah0[mt][3] = Ah.w;
            al0[mt][0] = Al.x; al0[mt][1] = Al.y; al0[mt][2] = Al.z; al0[mt][3] = Al.w;
        }

        __syncthreads();   // sync_Z: z written; y reads done

        // stop decision for J = it-1: poll tag-published partials (no atomics),
        // overlapped with stage 2 (w0 only).
        if (it > 0 && wid == 0) {
            const int J = it - 1;
            const unsigned tagw = (unsigned)it;           // J + 1
            const unsigned long long* ring = g_sync + ((unsigned)(J & 3)) * NCTA;
            unsigned long long w0v, w1v, w2v, w3v;
            for (;;) {
                w0v = *((volatile const unsigned long long*)(ring + l));
                w1v = *((volatile const unsigned long long*)(ring + l + 32));
                w2v = *((volatile const unsigned long long*)(ring + l + 64));
                w3v = *((volatile const unsigned long long*)(ring + l + 96));
                bool ok = ((unsigned)(w0v >> 32) == tagw) &&
                          ((unsigned)(w1v >> 32) == tagw) &&
                          ((unsigned)(w2v >> 32) == tagw) &&
                          ((unsigned)(w3v >> 32) == tagw);
                if (__all_sync(0xFFFFFFFFu, ok)) break;
                __nanosleep(32);
            }
            float s = __uint_as_float((unsigned)w0v)
                    + __uint_as_float((unsigned)w1v)
                    + __uint_as_float((unsigned)w2v)
                    + __uint_as_float((unsigned)w3v);
            float tot = warp_sum(s);
            if (l == 0) {
                float denom = (it == 1) ? (float)PDIM : (float)KDIM;
                *s_stop = (sqrtf(tot) < TOL_C * denom) ? 1 : 0;
            }
        }

        // ===== stage 2: acc += (-linv*D^T) @ z =====
        #pragma unroll
        for (int ks = 0; ks < 3; ++ks) {
            uint32_t bh[2][2], bl[2][2];
            #pragma unroll
            for (int nt = 0; nt < 2; ++nt) {
                const int zoff = (wn * 16 + nt * 8 + g) * ZSTR + ks * 16 + i4 * 2;
                float2 a0 = *(const float2*)(Zp + zoff);
                float2 a1 = *(const float2*)(Zp + zoff + 8);
                split_pack(a0.x, a0.y, bh[nt][0], bl[nt][0]);
                split_pack(a1.x, a1.y, bh[nt][1], bl[nt][1]);
            }
            uint32_t ah[5][4], al[5][4];
            if (ks == 0) {
                #pragma unroll
                for (int mt = 0; mt < 5; ++mt)
                    #pragma unroll
                    for (int r = 0; r < 4; ++r) { ah[mt][r] = ah0[mt][r]; al[mt][r] = al0[mt][r]; }
            } else {
                #pragma unroll
                for (int mt = 0; mt < 5; ++mt) {
                    int fi = ((wm * 5 + mt) * 3 + ks) * 32 + l;
                    uint4 Ah = *(const uint4*)(smem + A2H_OFF + fi * 16);
                    uint4 Al = *(const uint4*)(smem + A2L_OFF + fi * 16);
                    ah[mt][0] = Ah.x; ah[mt][1] = Ah.y; ah[mt][2] = Ah.z; ah[mt][3] = Ah.w;
                    al[mt][0] = Al.x; al[mt][1] = Al.y; al[mt][2] = Al.z; al[mt][3] = Al.w;
                }
            }
            #pragma unroll
            for (int mt = 0; mt < 5; ++mt)
                #pragma unroll
                for (int nt = 0; nt < 2; ++nt)
                    mma_bf16(acc[mt * 2 + nt], ah[mt], bh[nt]);
            #pragma unroll
            for (int mt = 0; mt < 5; ++mt)
                #pragma unroll
                for (int nt = 0; nt < 2; ++nt)
                    mma_bf16(acc[mt * 2 + nt], ah[mt], bl[nt]);
            #pragma unroll
            for (int mt = 0; mt < 5; ++mt)
                #pragma unroll
                for (int nt = 0; nt < 2; ++nt)
                    mma_bf16(acc[mt * 2 + nt], al[mt], bh[nt]);
        }

        const float tt = tts_s[it];
        float dsum = 0.0f;

        // epilogue (speculative): v = acc + y_reg ; shrink ; momentum
        #pragma unroll
        for (int mt = 0; mt < 5; ++mt)
            #pragma unroll
            for (int nt = 0; nt < 2; ++nt)
                #pragma unroll
                for (int q = 0; q < 4; ++q) {
                    int ix  = (mt * 2 + nt) * 4 + q;
                    float v  = acc[mt * 2 + nt][q] + yreg[ix];
                    float a  = fabsf(v) - lambd;
                    float xn = (a > 0.0f) ? copysignf(a, v) : 0.0f;
                    float xo = xold[ix];
                    float d  = xn - xo;
                    dsum = fmaf(d, d, dsum);
                    float yn = fmaf(tt, d, xn);
                    xold[ix] = xn;
                    yreg[ix] = yn;
                    int row = wm * 80 + mt * 16 + g + ((q >> 1) << 3);
                    int col = wn * 16 + nt * 8 + i4 * 2 + (q & 1);
                    *(float*)(smem + Y_OFF + (col * YSTR + row) * 4) = yn;
                }

        float ws = warp_sum(dsum);
        if (l == 0) red[wid] = ws;
        __syncthreads();   // sync_B: y + red + s_stop visible

        if (it > 0 && *s_stop) {
            // rollback speculative epilogue: xo = xn - (y - xn)/tt  (tt>0 for it>=1)
            float inv_tt = 1.0f / tt;
            #pragma unroll
            for (int v = 0; v < 40; ++v)
                xold[v] = xold[v] - (yreg[v] - xold[v]) * inv_tt;
            break;
        }

        // publish tagged partial (single 8B store; no atomics, no fences)
        if (tid == 0) {
            float s = red[0];
            #pragma unroll
            for (int i = 1; i < 8; ++i) s += red[i];
            unsigned long long pack =
                (((unsigned long long)(unsigned)(it + 1)) << 32) |
                (unsigned long long)__float_as_uint(s);
            *((volatile unsigned long long*)(g_sync + ((unsigned)(it & 3)) * NCTA + cta)) = pack;
        }
    }

    // ---- output: out[(b*160 + row)*4096 + p0 + col] ----
    #pragma unroll
    for (int mt = 0; mt < 5; ++mt)
        #pragma unroll
        for (int nt = 0; nt < 2; ++nt)
            #pragma unroll
            for (int q = 0; q < 4; ++q) {
                int row = wm * 80 + mt * 16 + g + ((q >> 1) << 3);
                int col = wn * 16 + nt * 8 + i4 * 2 + (q & 1);
                out[((size_t)b * KDIM + row) * PDIM + p0 + col] =
                    xold[(mt * 2 + nt) * 4 + q];
            }
}

// ---------------- launch ----------------
extern "C" void kernel_launch(void* const* d_in, const int* in_sizes, int n_in,
                              void* d_out, int out_size) {
    const float* Drr    = (const float*)d_in[0];
    const float* Dtheta = (const float*)d_in[1];
    const float* x      = (const float*)d_in[2];
    float* out = (float*)d_out;

    cudaFuncSetAttribute(fista_kernel, cudaFuncAttributeMaxDynamicSharedMemorySize, SMEM_TOTAL);
    setup_kernel<<<1, 1024>>>(Drr, Dtheta);
    fista_kernel<<<NCTA, NTHREADS, SMEM_TOTAL>>>(x, out);
}